// round 6
// baseline (speedup 1.0000x reference)
#include <cuda_runtime.h>

#define NB 32
#define NC 256
#define NHW 3136
#define NHW4 784
#define NG 32
#define EPSV 1e-5f

#define GRID_BLOCKS 128
#define TPB 1024                   // 32 warps/block
#define WARPS_PER_BLOCK 32
#define PLANES_PER_STAGE (GRID_BLOCKS * WARPS_PER_BLOCK)   // 4096 = 16 batches
#define NSTAGE 2

__device__ float d_pooled[NB * NC];

// ---- software grid barrier (all 128 blocks guaranteed co-resident) ----
__device__ unsigned int g_bar_count = 0;
__device__ volatile unsigned int g_bar_gen = 0;

__device__ __forceinline__ void grid_barrier() {
    __syncthreads();
    if (threadIdx.x == 0) {
        unsigned int gen = g_bar_gen;
        __threadfence();                       // publish pooled[] writes
        if (atomicAdd(&g_bar_count, 1u) == GRID_BLOCKS - 1) {
            g_bar_count = 0;
            __threadfence();
            g_bar_gen = gen + 1;               // release
        } else {
            while (g_bar_gen == gen) { __nanosleep(64); }
        }
        __threadfence();                       // acquire
    }
    __syncthreads();
}

__global__ __launch_bounds__(TPB, 1)
void fused_kernel(const float* __restrict__ x, float* __restrict__ out,
                  const float* __restrict__ alpha_w,
                  const float* __restrict__ alpha_b,
                  const float* __restrict__ g_w,
                  const float* __restrict__ g_b,
                  const float* __restrict__ g_rm,
                  const float* __restrict__ g_rv,
                  const float* __restrict__ grp_w,
                  const float* __restrict__ grp_b,
                  const float* __restrict__ grp_rm,
                  const float* __restrict__ grp_rv) {
    const int wid  = threadIdx.x >> 5;
    const int lane = threadIdx.x & 31;

    #pragma unroll 1
    for (int stage = 0; stage < NSTAGE; stage++) {
        const int plane = stage * PLANES_PER_STAGE + blockIdx.x * WARPS_PER_BLOCK + wid;

        // ---------------- pool: one warp per plane ----------------
        {
            const float4* __restrict__ xp =
                reinterpret_cast<const float4*>(x) + (size_t)plane * NHW4;
            float s = 0.0f;
            float4 v[8];
            #pragma unroll
            for (int b = 0; b < 3; b++) {           // 3*8*32 = 768
                #pragma unroll
                for (int k = 0; k < 8; k++)
                    v[k] = xp[lane + (b * 8 + k) * 32];
                #pragma unroll
                for (int k = 0; k < 8; k++)
                    s += (v[k].x + v[k].y) + (v[k].z + v[k].w);
            }
            if (lane < 16) {                        // tail 16
                float4 t = xp[768 + lane];
                s += (t.x + t.y) + (t.z + t.w);
            }
            #pragma unroll
            for (int o = 16; o > 0; o >>= 1)
                s += __shfl_down_sync(0xffffffffu, s, o);
            if (lane == 0)
                d_pooled[plane] = s * (1.0f / (float)NHW);
        }

        grid_barrier();   // pooled[] of this stage now visible everywhere

        // -------- inline coefficients for this warp's plane --------
        const int bb = plane >> 8;
        const int c  = plane & 255;

        // alpha_b via 256-wide dot (coalesced, L2 hits)
        float acc = 0.0f;
        #pragma unroll
        for (int m = 0; m < 8; m++) {
            const int idx = lane + 32 * m;
            acc += d_pooled[bb * NC + idx] * alpha_w[idx];
        }
        // group ms/msh: lane-parallel over the 32 groups (cached, 128KB total)
        const int gidx = lane * NC + c;
        const float sg = grp_w[gidx] * rsqrtf(grp_rv[gidx] + EPSV);
        float ms  = sg;
        float msh = grp_b[gidx] - grp_rm[gidx] * sg;
        #pragma unroll
        for (int o = 16; o > 0; o >>= 1) {
            acc += __shfl_xor_sync(0xffffffffu, acc, o);
            ms  += __shfl_xor_sync(0xffffffffu, ms,  o);
            msh += __shfl_xor_sync(0xffffffffu, msh, o);
        }
        const float a  = 1.0f / (1.0f + expf(-(acc + alpha_b[0])));
        const float na = 1.0f - a;
        ms  *= (1.0f / (float)NG);
        msh *= (1.0f / (float)NG);
        const float gs  = g_w[c] * rsqrtf(g_rv[c] + EPSV);
        const float gsh = g_b[c] - g_rm[c] * gs;
        const float sc = na * gs  + a * ms;
        const float sf = na * gsh + a * msh;

        // ---------------- apply: reads are fresh L2 hits ----------------
        {
            const float4* __restrict__ xp =
                reinterpret_cast<const float4*>(x) + (size_t)plane * NHW4;
            float4* __restrict__ op =
                reinterpret_cast<float4*>(out) + (size_t)plane * NHW4;
            float4 v[8];
            #pragma unroll
            for (int b = 0; b < 3; b++) {
                #pragma unroll
                for (int k = 0; k < 8; k++)
                    v[k] = xp[lane + (b * 8 + k) * 32];
                #pragma unroll
                for (int k = 0; k < 8; k++) {
                    float4 r;
                    r.x = fmaf(v[k].x, sc, sf);
                    r.y = fmaf(v[k].y, sc, sf);
                    r.z = fmaf(v[k].z, sc, sf);
                    r.w = fmaf(v[k].w, sc, sf);
                    __stcs(&op[lane + (b * 8 + k) * 32], r);
                }
            }
            if (lane < 16) {
                float4 t = xp[768 + lane];
                float4 r;
                r.x = fmaf(t.x, sc, sf);
                r.y = fmaf(t.y, sc, sf);
                r.z = fmaf(t.z, sc, sf);
                r.w = fmaf(t.w, sc, sf);
                __stcs(&op[768 + lane], r);
            }
        }
        // no barrier needed before next stage: only cross-block dependency
        // (pooled of stage g+1) is protected by that stage's own barrier
    }
}

extern "C" void kernel_launch(void* const* d_in, const int* in_sizes, int n_in,
                              void* d_out, int out_size) {
    const float* x       = (const float*)d_in[0];
    // d_in[1] = labels (unused)
    const float* alpha_w = (const float*)d_in[2];
    const float* alpha_b = (const float*)d_in[3];
    const float* g_w     = (const float*)d_in[4];
    const float* g_b     = (const float*)d_in[5];
    const float* g_rm    = (const float*)d_in[6];
    const float* g_rv    = (const float*)d_in[7];
    const float* grp_w   = (const float*)d_in[8];
    const float* grp_b   = (const float*)d_in[9];
    const float* grp_rm  = (const float*)d_in[10];
    const float* grp_rv  = (const float*)d_in[11];
    float* out = (float*)d_out;

    fused_kernel<<<GRID_BLOCKS, TPB>>>(x, out,
                                       alpha_w, alpha_b,
                                       g_w, g_b, g_rm, g_rv,
                                       grp_w, grp_b, grp_rm, grp_rv);
}

// round 7
// speedup vs baseline: 1.2783x; 1.2783x over previous
#include <cuda_runtime.h>

#define NB 32
#define NC 256
#define NHW 3136
#define NHW4 784
#define NG 32
#define EPSV 1e-5f

#define GRID_BLOCKS 512
#define TPB 256
#define WARPS_PER_BLOCK 8
#define PLANES_PER_STAGE (GRID_BLOCKS * WARPS_PER_BLOCK)   // 4096 planes = 16 batches
#define NSTAGE 2

__device__ float d_pooled[NB * NC];

// ---- self-resetting grid barrier (all 512 blocks co-resident @4/SM) ----
__device__ unsigned int d_arrive[NSTAGE];
__device__ unsigned int d_depart[NSTAGE];

__device__ __forceinline__ void grid_barrier(int s) {
    __syncthreads();
    if (threadIdx.x == 0) {
        __threadfence();                                   // release pooled[]
        atomicAdd(&d_arrive[s], 1u);
        while (*(volatile unsigned int*)&d_arrive[s] < GRID_BLOCKS)
            __nanosleep(32);
        // all arrived; last departer resets both counters for next graph replay
        if (atomicAdd(&d_depart[s], 1u) == GRID_BLOCKS - 1) {
            d_arrive[s] = 0;
            __threadfence();
            d_depart[s] = 0;
        }
        __threadfence();                                   // acquire
    }
    __syncthreads();
}

__global__ __launch_bounds__(TPB, 4)
void fused_kernel(const float* __restrict__ x, float* __restrict__ out,
                  const float* __restrict__ alpha_w,
                  const float* __restrict__ alpha_b,
                  const float* __restrict__ g_w,
                  const float* __restrict__ g_b,
                  const float* __restrict__ g_rm,
                  const float* __restrict__ g_rv,
                  const float* __restrict__ grp_w,
                  const float* __restrict__ grp_b,
                  const float* __restrict__ grp_rm,
                  const float* __restrict__ grp_rv) {
    const int wid  = threadIdx.x >> 5;
    const int lane = threadIdx.x & 31;

    #pragma unroll 1
    for (int stage = 0; stage < NSTAGE; stage++) {
        const int plane = stage * PLANES_PER_STAGE + blockIdx.x * WARPS_PER_BLOCK + wid;

        // ---------------- pool: one warp per plane, 4x6 batched loads ----
        {
            const float4* __restrict__ xp =
                reinterpret_cast<const float4*>(x) + (size_t)plane * NHW4;
            float s = 0.0f;
            float4 v[6];
            #pragma unroll
            for (int b = 0; b < 4; b++) {           // 4*6*32 = 768
                #pragma unroll
                for (int k = 0; k < 6; k++)
                    v[k] = xp[lane + (b * 6 + k) * 32];
                #pragma unroll
                for (int k = 0; k < 6; k++)
                    s += (v[k].x + v[k].y) + (v[k].z + v[k].w);
            }
            if (lane < 16) {                        // tail 784-768 = 16
                float4 t = xp[768 + lane];
                s += (t.x + t.y) + (t.z + t.w);
            }
            #pragma unroll
            for (int o = 16; o > 0; o >>= 1)
                s += __shfl_down_sync(0xffffffffu, s, o);
            if (lane == 0)
                d_pooled[plane] = s * (1.0f / (float)NHW);
        }

        grid_barrier(stage);

        // -------- inline coefficients for this warp's plane --------
        const int bb = plane >> 8;
        const int c  = plane & 255;

        float acc = 0.0f;
        #pragma unroll
        for (int m = 0; m < 8; m++) {
            const int idx = lane + 32 * m;
            acc += d_pooled[bb * NC + idx] * alpha_w[idx];
        }
        const int gidx = lane * NC + c;
        const float sg = grp_w[gidx] * rsqrtf(grp_rv[gidx] + EPSV);
        float ms  = sg;
        float msh = grp_b[gidx] - grp_rm[gidx] * sg;
        #pragma unroll
        for (int o = 16; o > 0; o >>= 1) {
            acc += __shfl_xor_sync(0xffffffffu, acc, o);
            ms  += __shfl_xor_sync(0xffffffffu, ms,  o);
            msh += __shfl_xor_sync(0xffffffffu, msh, o);
        }
        const float a  = 1.0f / (1.0f + expf(-(acc + alpha_b[0])));
        const float na = 1.0f - a;
        ms  *= (1.0f / (float)NG);
        msh *= (1.0f / (float)NG);
        const float gs  = g_w[c] * rsqrtf(g_rv[c] + EPSV);
        const float gsh = g_b[c] - g_rm[c] * gs;
        const float sc = na * gs  + a * ms;
        const float sf = na * gsh + a * msh;

        // ---------------- apply: reads are fresh L2 hits ----------------
        {
            const float4* __restrict__ xp =
                reinterpret_cast<const float4*>(x) + (size_t)plane * NHW4;
            float4* __restrict__ op =
                reinterpret_cast<float4*>(out) + (size_t)plane * NHW4;
            float4 v[6];
            #pragma unroll
            for (int b = 0; b < 4; b++) {
                #pragma unroll
                for (int k = 0; k < 6; k++)
                    v[k] = xp[lane + (b * 6 + k) * 32];
                #pragma unroll
                for (int k = 0; k < 6; k++) {
                    float4 r;
                    r.x = fmaf(v[k].x, sc, sf);
                    r.y = fmaf(v[k].y, sc, sf);
                    r.z = fmaf(v[k].z, sc, sf);
                    r.w = fmaf(v[k].w, sc, sf);
                    __stcs(&op[lane + (b * 6 + k) * 32], r);
                }
            }
            if (lane < 16) {
                float4 t = xp[768 + lane];
                float4 r;
                r.x = fmaf(t.x, sc, sf);
                r.y = fmaf(t.y, sc, sf);
                r.z = fmaf(t.z, sc, sf);
                r.w = fmaf(t.w, sc, sf);
                __stcs(&op[768 + lane], r);
            }
        }
    }
}

extern "C" void kernel_launch(void* const* d_in, const int* in_sizes, int n_in,
                              void* d_out, int out_size) {
    const float* x       = (const float*)d_in[0];
    // d_in[1] = labels (unused)
    const float* alpha_w = (const float*)d_in[2];
    const float* alpha_b = (const float*)d_in[3];
    const float* g_w     = (const float*)d_in[4];
    const float* g_b     = (const float*)d_in[5];
    const float* g_rm    = (const float*)d_in[6];
    const float* g_rv    = (const float*)d_in[7];
    const float* grp_w   = (const float*)d_in[8];
    const float* grp_b   = (const float*)d_in[9];
    const float* grp_rm  = (const float*)d_in[10];
    const float* grp_rv  = (const float*)d_in[11];
    float* out = (float*)d_out;

    fused_kernel<<<GRID_BLOCKS, TPB>>>(x, out,
                                       alpha_w, alpha_b,
                                       g_w, g_b, g_rm, g_rv,
                                       grp_w, grp_b, grp_rm, grp_rv);
}

// round 8
// speedup vs baseline: 1.3011x; 1.0179x over previous
#include <cuda_runtime.h>

#define NB 32
#define NC 256
#define NHW 3136
#define NHW4 784
#define NG 32
#define EPSV 1e-5f

#define GRID_BLOCKS 512
#define TPB 256
#define WARPS_PER_BLOCK 8
#define PLANES_PER_STAGE (GRID_BLOCKS * WARPS_PER_BLOCK)   // 4096 planes = 16 batches
#define NSTAGE 2

__device__ float d_pooled[NB * NC];

// ---- self-resetting grid barrier (all 512 blocks co-resident @4/SM) ----
__device__ unsigned int d_arrive[NSTAGE];
__device__ unsigned int d_depart[NSTAGE];

__device__ __forceinline__ void grid_barrier(int s) {
    __syncthreads();
    if (threadIdx.x == 0) {
        __threadfence();                                   // release pooled[]
        atomicAdd(&d_arrive[s], 1u);
        while (*(volatile unsigned int*)&d_arrive[s] < GRID_BLOCKS)
            __nanosleep(32);
        // all arrived; last departer resets both counters for next graph replay
        if (atomicAdd(&d_depart[s], 1u) == GRID_BLOCKS - 1) {
            d_arrive[s] = 0;
            __threadfence();
            d_depart[s] = 0;
        }
        __threadfence();                                   // acquire
    }
    __syncthreads();
}

__global__ __launch_bounds__(TPB, 4)
void fused_kernel(const float* __restrict__ x, float* __restrict__ out,
                  const float* __restrict__ alpha_w,
                  const float* __restrict__ alpha_b,
                  const float* __restrict__ g_w,
                  const float* __restrict__ g_b,
                  const float* __restrict__ g_rm,
                  const float* __restrict__ g_rv,
                  const float* __restrict__ grp_w,
                  const float* __restrict__ grp_b,
                  const float* __restrict__ grp_rm,
                  const float* __restrict__ grp_rv) {
    const int wid  = threadIdx.x >> 5;
    const int lane = threadIdx.x & 31;

    #pragma unroll 1
    for (int stage = 0; stage < NSTAGE; stage++) {
        const int plane = stage * PLANES_PER_STAGE + blockIdx.x * WARPS_PER_BLOCK + wid;

        // ---------------- pool: one warp per plane, 4x6 batched loads ----
        {
            const float4* __restrict__ xp =
                reinterpret_cast<const float4*>(x) + (size_t)plane * NHW4;
            float s = 0.0f;
            float4 v[6];
            #pragma unroll
            for (int b = 0; b < 4; b++) {           // 4*6*32 = 768
                #pragma unroll
                for (int k = 0; k < 6; k++)
                    v[k] = xp[lane + (b * 6 + k) * 32];
                #pragma unroll
                for (int k = 0; k < 6; k++)
                    s += (v[k].x + v[k].y) + (v[k].z + v[k].w);
            }
            if (lane < 16) {                        // tail 784-768 = 16
                float4 t = xp[768 + lane];
                s += (t.x + t.y) + (t.z + t.w);
            }
            #pragma unroll
            for (int o = 16; o > 0; o >>= 1)
                s += __shfl_down_sync(0xffffffffu, s, o);
            if (lane == 0)
                d_pooled[plane] = s * (1.0f / (float)NHW);
        }

        grid_barrier(stage);

        // -------- inline coefficients for this warp's plane --------
        const int bb = plane >> 8;
        const int c  = plane & 255;

        float acc = 0.0f;
        #pragma unroll
        for (int m = 0; m < 8; m++) {
            const int idx = lane + 32 * m;
            acc += d_pooled[bb * NC + idx] * alpha_w[idx];
        }
        const int gidx = lane * NC + c;
        const float sg = grp_w[gidx] * rsqrtf(grp_rv[gidx] + EPSV);
        float ms  = sg;
        float msh = grp_b[gidx] - grp_rm[gidx] * sg;
        #pragma unroll
        for (int o = 16; o > 0; o >>= 1) {
            acc += __shfl_xor_sync(0xffffffffu, acc, o);
            ms  += __shfl_xor_sync(0xffffffffu, ms,  o);
            msh += __shfl_xor_sync(0xffffffffu, msh, o);
        }
        const float a  = 1.0f / (1.0f + expf(-(acc + alpha_b[0])));
        const float na = 1.0f - a;
        ms  *= (1.0f / (float)NG);
        msh *= (1.0f / (float)NG);
        const float gs  = g_w[c] * rsqrtf(g_rv[c] + EPSV);
        const float gsh = g_b[c] - g_rm[c] * gs;
        const float sc = na * gs  + a * ms;
        const float sf = na * gsh + a * msh;

        // ---------------- apply: reads are fresh L2 hits ----------------
        {
            const float4* __restrict__ xp =
                reinterpret_cast<const float4*>(x) + (size_t)plane * NHW4;
            float4* __restrict__ op =
                reinterpret_cast<float4*>(out) + (size_t)plane * NHW4;
            float4 v[6];
            #pragma unroll
            for (int b = 0; b < 4; b++) {
                #pragma unroll
                for (int k = 0; k < 6; k++)
                    v[k] = xp[lane + (b * 6 + k) * 32];
                #pragma unroll
                for (int k = 0; k < 6; k++) {
                    float4 r;
                    r.x = fmaf(v[k].x, sc, sf);
                    r.y = fmaf(v[k].y, sc, sf);
                    r.z = fmaf(v[k].z, sc, sf);
                    r.w = fmaf(v[k].w, sc, sf);
                    __stcs(&op[lane + (b * 6 + k) * 32], r);
                }
            }
            if (lane < 16) {
                float4 t = xp[768 + lane];
                float4 r;
                r.x = fmaf(t.x, sc, sf);
                r.y = fmaf(t.y, sc, sf);
                r.z = fmaf(t.z, sc, sf);
                r.w = fmaf(t.w, sc, sf);
                __stcs(&op[768 + lane], r);
            }
        }
    }
}

extern "C" void kernel_launch(void* const* d_in, const int* in_sizes, int n_in,
                              void* d_out, int out_size) {
    const float* x       = (const float*)d_in[0];
    // d_in[1] = labels (unused)
    const float* alpha_w = (const float*)d_in[2];
    const float* alpha_b = (const float*)d_in[3];
    const float* g_w     = (const float*)d_in[4];
    const float* g_b     = (const float*)d_in[5];
    const float* g_rm    = (const float*)d_in[6];
    const float* g_rv    = (const float*)d_in[7];
    const float* grp_w   = (const float*)d_in[8];
    const float* grp_b   = (const float*)d_in[9];
    const float* grp_rm  = (const float*)d_in[10];
    const float* grp_rv  = (const float*)d_in[11];
    float* out = (float*)d_out;

    fused_kernel<<<GRID_BLOCKS, TPB>>>(x, out,
                                       alpha_w, alpha_b,
                                       g_w, g_b, g_rm, g_rv,
                                       grp_w, grp_b, grp_rm, grp_rv);
}

// round 9
// speedup vs baseline: 1.3905x; 1.0687x over previous
#include <cuda_runtime.h>

#define NB 32
#define NC 256
#define NHW 3136
#define NHW4 784
#define HALF4 392            // float4 per half-plane
#define NG 32
#define EPSV 1e-5f

#define GRID_BLOCKS 592      // 4 * 148: fully co-resident at 4 blocks/SM
#define TPB 256
#define NSTAGE 2
#define PLANES_PER_STAGE 4096

__device__ float d_pooled[NB * NC];

// ---- grid barrier + work counters (graph-replay safe) ----
__device__ unsigned int bar_count = 0;
__device__ volatile unsigned int bar_gen = 0;
__device__ unsigned int pool_ctr[NSTAGE];    // zero-init at load
__device__ unsigned int apply_ctr[NSTAGE];

__device__ __forceinline__ void grid_barrier_reset(int s) {
    __syncthreads();
    if (threadIdx.x == 0) {
        const unsigned int gen = bar_gen;
        __threadfence();                                  // publish pooled[]
        if (atomicAdd(&bar_count, 1u) == GRID_BLOCKS - 1) {
            bar_count    = 0;
            pool_ctr[s]  = 0;   // fully consumed this replay
            apply_ctr[s] = 0;   // consumed last replay; next use is after release
            __threadfence();
            bar_gen = gen + 1;  // release
        } else {
            while (bar_gen == gen) __nanosleep(32);
        }
        __threadfence();                                  // acquire
    }
    __syncthreads();
}

__global__ __launch_bounds__(TPB, 4)
void fused_kernel(const float* __restrict__ x, float* __restrict__ out,
                  const float* __restrict__ alpha_w,
                  const float* __restrict__ alpha_b,
                  const float* __restrict__ g_w,
                  const float* __restrict__ g_b,
                  const float* __restrict__ g_rm,
                  const float* __restrict__ g_rv,
                  const float* __restrict__ grp_w,
                  const float* __restrict__ grp_b,
                  const float* __restrict__ grp_rm,
                  const float* __restrict__ grp_rv) {
    const int lane = threadIdx.x & 31;

    #pragma unroll 1
    for (int stage = 0; stage < NSTAGE; stage++) {

        // ---------- pool phase: steal whole planes ----------
        for (;;) {
            unsigned int p;
            if (lane == 0) p = atomicAdd(&pool_ctr[stage], 1u);
            p = __shfl_sync(0xffffffffu, p, 0);
            if (p >= PLANES_PER_STAGE) break;
            const int plane = stage * PLANES_PER_STAGE + (int)p;

            const float4* __restrict__ xp =
                reinterpret_cast<const float4*>(x) + (size_t)plane * NHW4;
            float s = 0.0f;
            float4 v[6];
            #pragma unroll
            for (int b = 0; b < 4; b++) {            // 4*6*32 = 768
                #pragma unroll
                for (int k = 0; k < 6; k++)
                    v[k] = xp[lane + (b * 6 + k) * 32];
                #pragma unroll
                for (int k = 0; k < 6; k++)
                    s += (v[k].x + v[k].y) + (v[k].z + v[k].w);
            }
            if (lane < 16) {                         // tail 16
                float4 t = xp[768 + lane];
                s += (t.x + t.y) + (t.z + t.w);
            }
            #pragma unroll
            for (int o = 16; o > 0; o >>= 1)
                s += __shfl_down_sync(0xffffffffu, s, o);
            if (lane == 0)
                d_pooled[plane] = s * (1.0f / (float)NHW);
        }

        grid_barrier_reset(stage);

        // ---------- apply phase: steal half-planes ----------
        for (;;) {
            unsigned int g;
            if (lane == 0) g = atomicAdd(&apply_ctr[stage], 1u);
            g = __shfl_sync(0xffffffffu, g, 0);
            if (g >= 2u * PLANES_PER_STAGE) break;
            const int plane = stage * PLANES_PER_STAGE + (int)(g >> 1);
            const int base  = (g & 1u) ? HALF4 : 0;

            // per-plane coefficients (warp-collective, cached reads)
            const int bb = plane >> 8;
            const int c  = plane & 255;
            float acc = 0.0f;
            #pragma unroll
            for (int m = 0; m < 8; m++) {
                const int idx = lane + 32 * m;
                acc += d_pooled[bb * NC + idx] * alpha_w[idx];
            }
            const int gidx = lane * NC + c;
            const float sgv = grp_w[gidx] * rsqrtf(grp_rv[gidx] + EPSV);
            float ms  = sgv;
            float msh = grp_b[gidx] - grp_rm[gidx] * sgv;
            #pragma unroll
            for (int o = 16; o > 0; o >>= 1) {
                acc += __shfl_xor_sync(0xffffffffu, acc, o);
                ms  += __shfl_xor_sync(0xffffffffu, ms,  o);
                msh += __shfl_xor_sync(0xffffffffu, msh, o);
            }
            const float a  = 1.0f / (1.0f + expf(-(acc + alpha_b[0])));
            const float na = 1.0f - a;
            ms  *= (1.0f / (float)NG);
            msh *= (1.0f / (float)NG);
            const float gsv = g_w[c] * rsqrtf(g_rv[c] + EPSV);
            const float gsh = g_b[c] - g_rm[c] * gsv;
            const float sc = na * gsv + a * ms;
            const float sf = na * gsh + a * msh;

            const float4* __restrict__ xp =
                reinterpret_cast<const float4*>(x) + (size_t)plane * NHW4 + base;
            float4* __restrict__ op =
                reinterpret_cast<float4*>(out) + (size_t)plane * NHW4 + base;

            float4 v[6];
            #pragma unroll
            for (int b = 0; b < 2; b++) {            // 2*6*32 = 384
                #pragma unroll
                for (int k = 0; k < 6; k++)
                    v[k] = xp[lane + (b * 6 + k) * 32];   // L2 hits (staged)
                #pragma unroll
                for (int k = 0; k < 6; k++) {
                    float4 r;
                    r.x = fmaf(v[k].x, sc, sf);
                    r.y = fmaf(v[k].y, sc, sf);
                    r.z = fmaf(v[k].z, sc, sf);
                    r.w = fmaf(v[k].w, sc, sf);
                    __stcs(&op[lane + (b * 6 + k) * 32], r);
                }
            }
            if (lane < 8) {                          // tail 392-384 = 8
                float4 t = xp[384 + lane];
                float4 r;
                r.x = fmaf(t.x, sc, sf);
                r.y = fmaf(t.y, sc, sf);
                r.z = fmaf(t.z, sc, sf);
                r.w = fmaf(t.w, sc, sf);
                __stcs(&op[384 + lane], r);
            }
        }
        // no barrier after apply: next stage's pool uses its own counters,
        // and its barrier orders pooled[] before that stage's apply.
    }
}

extern "C" void kernel_launch(void* const* d_in, const int* in_sizes, int n_in,
                              void* d_out, int out_size) {
    const float* x       = (const float*)d_in[0];
    // d_in[1] = labels (unused)
    const float* alpha_w = (const float*)d_in[2];
    const float* alpha_b = (const float*)d_in[3];
    const float* g_w     = (const float*)d_in[4];
    const float* g_b     = (const float*)d_in[5];
    const float* g_rm    = (const float*)d_in[6];
    const float* g_rv    = (const float*)d_in[7];
    const float* grp_w   = (const float*)d_in[8];
    const float* grp_b   = (const float*)d_in[9];
    const float* grp_rm  = (const float*)d_in[10];
    const float* grp_rv  = (const float*)d_in[11];
    float* out = (float*)d_out;

    fused_kernel<<<GRID_BLOCKS, TPB>>>(x, out,
                                       alpha_w, alpha_b,
                                       g_w, g_b, g_rm, g_rv,
                                       grp_w, grp_b, grp_rm, grp_rv);
}